// round 6
// baseline (speedup 1.0000x reference)
#include <cuda_runtime.h>
#include <math_constants.h>

// pix_attn: fused window-attention over 3x3 reflected windows.
// Grid: 512 blocks = (b=8) x (h=64). Block = 256 threads = 8 warps.
// Each warp processes 8 pixels (one per iteration) of its row.
//
// Per-pixel math (derived from reference):
//   P[m] = x[b, m/9, refl(h + (m%9)/3 - 1), refl(w + (m%9)%3 - 1)], m in [0,576)
//   token l (1..9) activation row c = P[64*(l-1)+c]   (contiguous in m!)
//   token 0 output = mean over l of token-l pre-bias output + bias
//                  = mean of biased outputs (since all share one bias).
//   qk = x_raw @ Wqk + bqk ; kv = xf @ Wkv + bkv ; softmax over 10 logits + qdot;
//   out = (attn@v + attn_self*q_) @ Wproj + bproj.

#define SM_TILE   (3 * 64 * 64)     // 12288 floats: [wi][ch][w]
#define SM_KV     (8 * 10 * 128)    // per-warp kv scratch
#define SM_QK     (8 * 128)
#define SM_ATT    (8 * 96)          // [h][12] per warp (11 used)
#define SM_OUT    (8 * 64)
#define SMEM_FLOATS (SM_TILE + SM_KV + SM_QK + SM_ATT + SM_OUT)

__global__ __launch_bounds__(256, 2)
void pix_attn_kernel(const float* __restrict__ x,
                     const float* __restrict__ Wqk,  const float* __restrict__ bqk,
                     const float* __restrict__ Wkv,  const float* __restrict__ bkv,
                     const float* __restrict__ Wproj,const float* __restrict__ bproj,
                     float* __restrict__ out)
{
    extern __shared__ float sm[];
    float* tile  = sm;                       // [3][64][64]
    float* kv_s  = tile + SM_TILE;
    float* qk_s  = kv_s + SM_KV;
    float* att_s = qk_s + SM_QK;
    float* out_s = att_s + SM_ATT;

    const int tid = threadIdx.x;
    const int wid = tid >> 5;
    const int ln  = tid & 31;
    const int blk = blockIdx.x;
    const int b_  = blk >> 6;
    const int h   = blk & 63;

    // ---- load 3 reflected rows of all 64 channels into smem (coalesced) ----
    const int r0 = (h == 0)  ? 1  : h - 1;
    const int r2 = (h == 63) ? 62 : h + 1;
    const float* xb = x + (size_t)b_ * 64 * 64 * 64;
    #pragma unroll
    for (int wi = 0; wi < 3; ++wi) {
        const int r = (wi == 0) ? r0 : ((wi == 1) ? h : r2);
        for (int idx = tid; idx < 4096; idx += 256) {
            const int ch = idx >> 6;
            const int wc = idx & 63;
            tile[wi * 4096 + idx] = xb[ch * 4096 + r * 64 + wc];
        }
    }
    __syncthreads();

    float* kvw  = kv_s  + wid * 1280;
    float* qkw  = qk_s  + wid * 128;
    float* attw = att_s + wid * 96;
    float* outw = out_s + wid * 64;

    const float4 bias_qk = *(const float4*)(bqk + 4 * ln);
    const float4 bias_kv = *(const float4*)(bkv + 4 * ln);
    const float2 bias_pj = *(const float2*)(bproj + 2 * ln);
    const float scale = 0.35355339059327373f;  // 8^-0.5

    for (int it = 0; it < 8; ++it) {
        const int w   = wid * 8 + it;
        const int cm1 = (w == 0)  ? 1  : w - 1;
        const int cp1 = (w == 63) ? 62 : w + 1;
        const int cols[3] = {cm1, w, cp1};

        // base pointers: bp[wp] + ch*64 == patch(ch, wp)
        const float* bp[9];
        #pragma unroll
        for (int wp = 0; wp < 9; ++wp)
            bp[wp] = tile + (wp / 3) * 4096 + cols[wp % 3];

        // ---- qk projection: lane computes outputs 4ln..4ln+3 ----
        float4 aq = bias_qk;
        #pragma unroll
        for (int c = 0; c < 64; ++c) {
            const float xr = bp[4][c * 64];           // x_raw[c] = center tap
            const float4 wr = __ldg((const float4*)(Wqk + c * 128 + 4 * ln));
            aq.x += xr * wr.x; aq.y += xr * wr.y;
            aq.z += xr * wr.z; aq.w += xr * wr.w;
        }
        *(float4*)(qkw + 4 * ln) = aq;

        // ---- kv GEMM, tokens 1..9 accumulated together ----
        float4 acc[9];
        #pragma unroll
        for (int l = 0; l < 9; ++l) acc[l] = bias_kv;

        #pragma unroll
        for (int c = 0; c < 64; ++c) {
            const float4 wr = __ldg((const float4*)(Wkv + c * 128 + 4 * ln));
            #pragma unroll
            for (int l = 0; l < 9; ++l) {
                const int m = 64 * l + c;             // compile-time constant
                const float v = bp[m % 9][(m / 9) * 64];
                acc[l].x += v * wr.x; acc[l].y += v * wr.y;
                acc[l].z += v * wr.z; acc[l].w += v * wr.w;
            }
        }
        // token 0 (pooled-global) = mean of biased tokens 1..9
        float4 a0 = make_float4(0.f, 0.f, 0.f, 0.f);
        #pragma unroll
        for (int l = 0; l < 9; ++l) {
            a0.x += acc[l].x; a0.y += acc[l].y;
            a0.z += acc[l].z; a0.w += acc[l].w;
        }
        const float inv9 = 1.0f / 9.0f;
        a0.x *= inv9; a0.y *= inv9; a0.z *= inv9; a0.w *= inv9;

        *(float4*)(kvw + 4 * ln) = a0;
        #pragma unroll
        for (int l = 0; l < 9; ++l)
            *(float4*)(kvw + (l + 1) * 128 + 4 * ln) = acc[l];
        __syncwarp();

        // ---- logits: 80 dot products of length 8 spread over lanes ----
        for (int t = ln; t < 80; t += 32) {
            const int hh = t & 7, n = t >> 3;
            float d = 0.f;
            #pragma unroll
            for (int dd = 0; dd < 8; ++dd)
                d += qkw[hh * 8 + dd] * kvw[n * 128 + hh * 8 + dd];
            attw[hh * 12 + n] = d * scale;
        }
        if (ln < 8) {
            float qv = 0.f;
            #pragma unroll
            for (int dd = 0; dd < 8; ++dd)
                qv += qkw[ln * 8 + dd] * qkw[64 + ln * 8 + dd];
            attw[ln * 12 + 10] = qv;   // self logit (no scale)
        }
        __syncwarp();

        // ---- softmax over 11, one head per lane (lanes 0..7) ----
        if (ln < 8) {
            float vv[11];
            float mx = -CUDART_INF_F;
            #pragma unroll
            for (int n = 0; n < 11; ++n) { vv[n] = attw[ln * 12 + n]; mx = fmaxf(mx, vv[n]); }
            float s = 0.f;
            #pragma unroll
            for (int n = 0; n < 11; ++n) { vv[n] = __expf(vv[n] - mx); s += vv[n]; }
            const float inv = __fdividef(1.0f, s);
            #pragma unroll
            for (int n = 0; n < 11; ++n) attw[ln * 12 + n] = vv[n] * inv;
        }
        __syncwarp();

        // ---- fusion + sole: lane handles outputs ln, ln+32 ----
        #pragma unroll
        for (int rep = 0; rep < 2; ++rep) {
            const int o  = ln + rep * 32;
            const int hh = o >> 3;
            float r = attw[hh * 12 + 10] * qkw[64 + o];
            #pragma unroll
            for (int n = 0; n < 10; ++n)
                r += attw[hh * 12 + n] * kvw[n * 128 + 64 + o];
            outw[o] = r;
        }
        __syncwarp();

        // ---- proj: lane computes channels 2ln, 2ln+1 ----
        float2 ap = bias_pj;
        #pragma unroll
        for (int c = 0; c < 64; ++c) {
            const float xo = outw[c];
            const float2 wr = __ldg((const float2*)(Wproj + c * 64 + 2 * ln));
            ap.x += xo * wr.x; ap.y += xo * wr.y;
        }
        float* og = out + ((size_t)b_ * 64 + 2 * ln) * 4096 + h * 64 + w;
        og[0]    = ap.x;
        og[4096] = ap.y;
        __syncwarp();   // smem scratch reused next pixel
    }
}

extern "C" void kernel_launch(void* const* d_in, const int* in_sizes, int n_in,
                              void* d_out, int out_size)
{
    const float* x     = (const float*)d_in[0];
    const float* Wqk   = (const float*)d_in[1];
    const float* bqk   = (const float*)d_in[2];
    const float* Wkv   = (const float*)d_in[3];
    const float* bkv   = (const float*)d_in[4];
    const float* Wproj = (const float*)d_in[5];
    const float* bproj = (const float*)d_in[6];
    float* out = (float*)d_out;

    const int smem_bytes = SMEM_FLOATS * (int)sizeof(float);
    cudaFuncSetAttribute(pix_attn_kernel,
                         cudaFuncAttributeMaxDynamicSharedMemorySize, smem_bytes);

    pix_attn_kernel<<<512, 256, smem_bytes>>>(x, Wqk, bqk, Wkv, bkv, Wproj, bproj, out);
}

// round 17
// speedup vs baseline: 1.2186x; 1.2186x over previous
#include <cuda_runtime.h>
#include <math_constants.h>

// pix_attn: fused window-attention over 3x3 reflected windows.
// Grid: 512 blocks = (b=8) x (h=64). Block = 256 threads = 8 warps.
// Each warp processes 8 pixels. R7: packed f32x2 FMA + register-resident
// attention epilogue (lane ln owns kv cols 4ln..4ln+3; lanes 0-15 = q/k,
// lanes 16-31 = q_/v, head = (ln&15)/2 -- all attention math in-lane/shfl).

typedef unsigned long long u64;

__device__ __forceinline__ u64 pack2(float a, float b) {
    u64 r; asm("mov.b64 %0, {%1, %2};" : "=l"(r) : "f"(a), "f"(b)); return r;
}
__device__ __forceinline__ void unpack2(u64 v, float& a, float& b) {
    asm("mov.b64 {%0, %1}, %2;" : "=f"(a), "=f"(b) : "l"(v));
}
__device__ __forceinline__ void fma2(u64& d, u64 a, u64 b) {
    asm("fma.rn.f32x2 %0, %1, %2, %0;" : "+l"(d) : "l"(a), "l"(b));
}
__device__ __forceinline__ u64 add2(u64 a, u64 b) {
    u64 r; asm("add.rn.f32x2 %0, %1, %2;" : "=l"(r) : "l"(a), "l"(b)); return r;
}
__device__ __forceinline__ u64 mul2(u64 a, u64 b) {
    u64 r; asm("mul.rn.f32x2 %0, %1, %2;" : "=l"(r) : "l"(a), "l"(b)); return r;
}

#define SM_TILE   (3 * 64 * 64)     // 12288 floats: [wi][ch][w]
#define SM_OUT    (8 * 64)          // per-warp proj input
#define SMEM_FLOATS (SM_TILE + SM_OUT)

__global__ __launch_bounds__(256, 2)
void pix_attn_kernel(const float* __restrict__ x,
                     const float* __restrict__ Wqk,  const float* __restrict__ bqk,
                     const float* __restrict__ Wkv,  const float* __restrict__ bkv,
                     const float* __restrict__ Wproj,const float* __restrict__ bproj,
                     float* __restrict__ out)
{
    extern __shared__ float sm[];
    float* tile  = sm;                       // [3][64][64]
    float* out_s = tile + SM_TILE;

    const int tid = threadIdx.x;
    const int wid = tid >> 5;
    const int ln  = tid & 31;
    const int blk = blockIdx.x;
    const int b_  = blk >> 6;
    const int h   = blk & 63;

    // ---- load 3 reflected rows of all 64 channels into smem (coalesced) ----
    const int r0 = (h == 0)  ? 1  : h - 1;
    const int r2 = (h == 63) ? 62 : h + 1;
    const float* xb = x + (size_t)b_ * 64 * 64 * 64;
    #pragma unroll
    for (int wi = 0; wi < 3; ++wi) {
        const int r = (wi == 0) ? r0 : ((wi == 1) ? h : r2);
        for (int idx = tid; idx < 4096; idx += 256) {
            tile[wi * 4096 + idx] = xb[(idx >> 6) * 4096 + r * 64 + (idx & 63)];
        }
    }
    __syncthreads();

    float* outw = out_s + wid * 64;

    const float4 bqk4 = *(const float4*)(bqk + 4 * ln);
    const u64 bqk_a = pack2(bqk4.x, bqk4.y), bqk_b = pack2(bqk4.z, bqk4.w);
    const float4 bkv4 = *(const float4*)(bkv + 4 * ln);
    const u64 bkv_a = pack2(bkv4.x, bkv4.y), bkv_b = pack2(bkv4.z, bkv4.w);
    const float2 bpj2 = *(const float2*)(bproj + 2 * ln);
    const u64 bpj = pack2(bpj2.x, bpj2.y);
    const float scale = 0.35355339059327373f;  // 8^-0.5
    const u64 ninth = pack2(1.0f / 9.0f, 1.0f / 9.0f);

    for (int it = 0; it < 8; ++it) {
        const int w   = wid * 8 + it;
        const int cm1 = (w == 0)  ? 1  : w - 1;
        const int cp1 = (w == 63) ? 62 : w + 1;
        const int cols[3] = {cm1, w, cp1};

        // bp[wp] + ch*64 == patch(ch, wp)
        const float* bp[9];
        #pragma unroll
        for (int wp = 0; wp < 9; ++wp)
            bp[wp] = tile + (wp / 3) * 4096 + cols[wp % 3];

        // ---- qk projection: lane computes cols 4ln..4ln+3 of [q | q_] ----
        u64 aq0 = bqk_a, aq1 = bqk_b;
        #pragma unroll
        for (int c = 0; c < 64; ++c) {
            const float xr = bp[4][c * 64];           // x_raw[c] = center tap
            const u64 xx = pack2(xr, xr);
            const ulonglong2 wv = __ldg((const ulonglong2*)(Wqk + c * 128 + 4 * ln));
            fma2(aq0, xx, wv.x);
            fma2(aq1, xx, wv.y);
        }
        float q4[4];
        unpack2(aq0, q4[0], q4[1]);
        unpack2(aq1, q4[2], q4[3]);

        // ---- kv GEMM, tokens 1..9 accumulated together (packed f32x2) ----
        u64 acc[18];
        #pragma unroll
        for (int l = 0; l < 9; ++l) { acc[2 * l] = bkv_a; acc[2 * l + 1] = bkv_b; }

        #pragma unroll
        for (int c = 0; c < 64; ++c) {
            const ulonglong2 wv = __ldg((const ulonglong2*)(Wkv + c * 128 + 4 * ln));
            #pragma unroll
            for (int l = 0; l < 9; ++l) {
                const int m = 64 * l + c;             // compile-time constant
                const float v = bp[m % 9][(m / 9) * 64];
                const u64 vv = pack2(v, v);
                fma2(acc[2 * l],     vv, wv.x);
                fma2(acc[2 * l + 1], vv, wv.y);
            }
        }
        // token 0 (pooled-global) = mean of biased tokens 1..9
        u64 s0 = acc[0], s1 = acc[1];
        #pragma unroll
        for (int l = 1; l < 9; ++l) { s0 = add2(s0, acc[2 * l]); s1 = add2(s1, acc[2 * l + 1]); }
        s0 = mul2(s0, ninth); s1 = mul2(s1, ninth);

        // unpack tokens: tok[n][j] = kv[token n][col 4ln+j], n=0 pooled, 1..9 window
        float tok[10][4];
        unpack2(s0, tok[0][0], tok[0][1]);
        unpack2(s1, tok[0][2], tok[0][3]);
        #pragma unroll
        for (int l = 0; l < 9; ++l) {
            unpack2(acc[2 * l],     tok[l + 1][0], tok[l + 1][1]);
            unpack2(acc[2 * l + 1], tok[l + 1][2], tok[l + 1][3]);
        }

        // ---- logits, register-resident (meaningful in lanes 0..15) ----
        // lane ln<16: q4 = q[head ln/2, d=(ln%2)*4 ..+3], tok = k same cols.
        float lg[11];
        #pragma unroll
        for (int n = 0; n < 10; ++n) {
            float p = q4[0] * tok[n][0] + q4[1] * tok[n][1]
                    + q4[2] * tok[n][2] + q4[3] * tok[n][3];
            p += __shfl_xor_sync(0xffffffffu, p, 1);   // pair-reduce within head
            lg[n] = p * scale;
        }
        // q_value = sum_d q*q_ : q in lane t, q_ in lane t+16 (same cols +64)
        float qv = 0.f;
        #pragma unroll
        for (int j = 0; j < 4; ++j)
            qv += q4[j] * __shfl_xor_sync(0xffffffffu, q4[j], 16);
        qv += __shfl_xor_sync(0xffffffffu, qv, 1);
        lg[10] = qv;                                    // self logit (no scale)

        // ---- softmax over 11 (valid in lanes 0..15; upper lanes garbage, unused) ----
        float mx = lg[0];
        #pragma unroll
        for (int n = 1; n < 11; ++n) mx = fmaxf(mx, lg[n]);
        float ssum = 0.f;
        #pragma unroll
        for (int n = 0; n < 11; ++n) { lg[n] = __expf(lg[n] - mx); ssum += lg[n]; }
        const float inv = __fdividef(1.0f, ssum);
        #pragma unroll
        for (int n = 0; n < 11; ++n) lg[n] *= inv;
        // broadcast attn to upper half (source lane = ln&15, a no-op for low lanes)
        #pragma unroll
        for (int n = 0; n < 11; ++n) lg[n] = __shfl_sync(0xffffffffu, lg[n], ln & 15);

        // ---- fusion + sole, in-lane in lanes 16..31 (tok = v, q4 = q_) ----
        float r4[4];
        #pragma unroll
        for (int j = 0; j < 4; ++j) {
            float r = lg[10] * q4[j];
            #pragma unroll
            for (int n = 0; n < 10; ++n) r += lg[n] * tok[n][j];
            r4[j] = r;
        }
        if (ln >= 16)
            *(float4*)(outw + 4 * (ln - 16)) = make_float4(r4[0], r4[1], r4[2], r4[3]);
        __syncwarp();

        // ---- proj: lane computes channels 2ln, 2ln+1 (packed) ----
        u64 ap = bpj;
        #pragma unroll
        for (int c = 0; c < 64; ++c) {
            const float xo = outw[c];
            const u64 xx = pack2(xo, xo);
            const u64 wv = __ldg((const u64*)(Wproj + c * 64 + 2 * ln));
            fma2(ap, xx, wv);
        }
        float o0, o1;
        unpack2(ap, o0, o1);
        float* og = out + ((size_t)b_ * 64 + 2 * ln) * 4096 + h * 64 + w;
        og[0]    = o0;
        og[4096] = o1;
        __syncwarp();   // outw reused next pixel
    }
}

extern "C" void kernel_launch(void* const* d_in, const int* in_sizes, int n_in,
                              void* d_out, int out_size)
{
    const float* x     = (const float*)d_in[0];
    const float* Wqk   = (const float*)d_in[1];
    const float* bqk   = (const float*)d_in[2];
    const float* Wkv   = (const float*)d_in[3];
    const float* bkv   = (const float*)d_in[4];
    const float* Wproj = (const float*)d_in[5];
    const float* bproj = (const float*)d_in[6];
    float* out = (float*)d_out;

    const int smem_bytes = SMEM_FLOATS * (int)sizeof(float);
    cudaFuncSetAttribute(pix_attn_kernel,
                         cudaFuncAttributeMaxDynamicSharedMemorySize, smem_bytes);

    pix_attn_kernel<<<512, 256, smem_bytes>>>(x, Wqk, bqk, Wkv, bkv, Wproj, bproj, out);
}